// round 6
// baseline (speedup 1.0000x reference)
#include <cuda_runtime.h>
#include <cuda_fp16.h>
#include <cstdint>

#define N_NODES 100000
#define N_EDGES 1600000
#define D_IN    512
#define D_OUT   64

#define SCAN_BLK 1024
#define N_SCAN_BLKS ((N_NODES + SCAN_BLK - 1) / SCAN_BLK)   // 98

#define TILE_M  256
#define TILES   391            // ceil(100000/256)
#define GGRID   152
#define NTHREADS 512

#define CHUNK_K 64
#define BS 72                  // halves per W row in smem (64 + 8 pad)
#define AS 72                  // halves per A row in smem (64 + 8 pad)
#define B_SMEM_HALVES (D_IN * BS)            // 36864  (73728 B)
#define A_SMEM_HALVES (TILE_M * AS)          // 18432 per buffer (36864 B)
#define SMEM_TOTAL ((B_SMEM_HALVES + 2 * A_SMEM_HALVES) * 2)  // 147456 B

// ---------------- scratch -----------------------------------------------------
__device__ __half g_h[N_NODES * D_OUT];      // 12.8 MB fp16
__device__ int   g_deg[N_NODES];
__device__ int   g_rowstart[N_NODES + 1];
__device__ int   g_cursor[N_NODES];
__device__ int   g_bsum[128];
__device__ int   g_csr_col[N_EDGES];
__device__ float g_csr_val[N_EDGES];

// ---------------- helpers -----------------------------------------------------
__device__ __forceinline__ uint32_t smem_u32(const void* p) {
    uint32_t a;
    asm("{ .reg .u64 t; cvta.to.shared.u64 t, %1; cvt.u32.u64 %0, t; }"
        : "=r"(a) : "l"(p));
    return a;
}

__device__ __forceinline__ uint32_t pack_h2(float lo, float hi) {
    __half2 h = __floats2half2_rn(lo, hi);
    return *reinterpret_cast<uint32_t*>(&h);
}

__device__ __forceinline__ void ldsm_x4(uint32_t addr, uint32_t r[4]) {
    asm volatile("ldmatrix.sync.aligned.m8n8.x4.shared.b16 {%0,%1,%2,%3}, [%4];"
                 : "=r"(r[0]), "=r"(r[1]), "=r"(r[2]), "=r"(r[3]) : "r"(addr));
}

__device__ __forceinline__ void ldsm_x4_t(uint32_t addr, uint32_t r[4]) {
    asm volatile("ldmatrix.sync.aligned.m8n8.x4.trans.shared.b16 {%0,%1,%2,%3}, [%4];"
                 : "=r"(r[0]), "=r"(r[1]), "=r"(r[2]), "=r"(r[3]) : "r"(addr));
}

__device__ __forceinline__ void mma_f16(float c[4], const uint32_t a[4],
                                        uint32_t b0, uint32_t b1) {
    asm volatile(
        "mma.sync.aligned.m16n8k16.row.col.f32.f16.f16.f32 "
        "{%0,%1,%2,%3}, {%4,%5,%6,%7}, {%8,%9}, {%0,%1,%2,%3};"
        : "+f"(c[0]), "+f"(c[1]), "+f"(c[2]), "+f"(c[3])
        : "r"(a[0]), "r"(a[1]), "r"(a[2]), "r"(a[3]), "r"(b0), "r"(b1));
}

// prefetch one 64-col half-row (32 floats) and convert to 8 packed half2
__device__ __forceinline__ void pf_load(const float* __restrict__ p, bool ok,
                                        uint2 ph[8]) {
    #pragma unroll
    for (int j = 0; j < 8; j++) {
        float4 v = ok ? *(const float4*)(p + 4 * j) : make_float4(0.f, 0.f, 0.f, 0.f);
        ph[j] = make_uint2(pack_h2(v.x, v.y), pack_h2(v.z, v.w));
    }
}

__device__ __forceinline__ void pf_store(__half* d, const uint2 ph[8]) {
    #pragma unroll
    for (int j = 0; j < 4; j++) {
        *(uint4*)(d + 8 * j) = make_uint4(ph[2*j].x, ph[2*j].y, ph[2*j+1].x, ph[2*j+1].y);
    }
}

// ---------------- GEMM: h = X @ W, fp16 mma, 64-col chunks --------------------
__global__ __launch_bounds__(NTHREADS, 1) void k_gemm_tc(const float* __restrict__ X,
                                                         const float* __restrict__ W) {
    extern __shared__ __align__(16) __half hsm[];
    __half* const Bsm = hsm;                       // [512][72]
    __half* const Asm = hsm + B_SMEM_HALVES;       // 2 x [256][72]

    const int tid  = threadIdx.x;
    const int bx   = blockIdx.x;
    const int warp = tid >> 5;        // 0..15
    const int lane = tid & 31;
    const int grp  = lane >> 2;
    const int tig  = lane & 3;
    const int moff = warp * 16;

    const uint32_t b_base = smem_u32(Bsm);
    const uint32_t a_base = smem_u32(Asm);

    // ---- W -> smem fp16 [k][n] stride 72 ----
    for (int i = tid * 4; i < D_IN * D_OUT; i += NTHREADS * 4) {
        const int kk = i >> 6, nn = i & 63;
        float4 v = *(const float4*)&W[i];
        *(uint2*)(Bsm + kk * BS + nn) = make_uint2(pack_h2(v.x, v.y), pack_h2(v.z, v.w));
    }

    const int my_tiles = (TILES - bx + GGRID - 1) / GGRID;
    const int nchunks  = my_tiles * 8;             // 8 chunks of 64 cols per tile
    if (nchunks == 0) return;

    const int arow = tid >> 1;            // 0..255
    const int acol = (tid & 1) * 32;      // half-row (32 floats)

    uint2 ph[8];
    {   // prologue: chunk 0 -> buffer 0
        const int grow = bx * TILE_M + arow;
        pf_load(X + (size_t)grow * D_IN + acol, grow < N_NODES, ph);
        pf_store(Asm + arow * AS + acol, ph);
    }

    float acc[8][4];
    #pragma unroll
    for (int j = 0; j < 8; j++)
        #pragma unroll
        for (int e = 0; e < 4; e++) acc[j][e] = 0.f;

    const int l15 = lane & 15;
    const int lhi = (lane >> 4) << 3;

    for (int c = 0; c < nchunks; c++) {
        if (c + 1 < nchunks) {   // prefetch + convert next chunk in regs
            const int tile = bx + ((c + 1) >> 3) * GGRID;
            const int grow = tile * TILE_M + arow;
            const int k0   = ((c + 1) & 7) * CHUNK_K + acol;
            pf_load(X + (size_t)grow * D_IN + k0, grow < N_NODES, ph);
        }

        __syncthreads();

        // ---- compute chunk c (4 k-steps of 16) ----
        const uint32_t abuf = a_base + (uint32_t)(c & 1) * (A_SMEM_HALVES * 2);
        const int kbase = (c & 7) * CHUNK_K;
        #pragma unroll
        for (int ks = 0; ks < 4; ks++) {
            uint32_t a[4];
            ldsm_x4(abuf + 2 * ((moff + l15) * AS + ks * 16 + lhi), a);

            uint32_t b[8][2];
            const int kb = kbase + ks * 16;
            #pragma unroll
            for (int jj = 0; jj < 4; jj++) {
                uint32_t br[4];
                ldsm_x4_t(b_base + 2 * ((kb + l15) * BS + jj * 16 + lhi), br);
                b[2*jj][0]   = br[0];  b[2*jj][1]   = br[1];
                b[2*jj+1][0] = br[2];  b[2*jj+1][1] = br[3];
            }
            #pragma unroll
            for (int j = 0; j < 8; j++)
                mma_f16(acc[j], a, b[j][0], b[j][1]);
        }

        if (c + 1 < nchunks) {
            pf_store(Asm + (size_t)((c + 1) & 1) * A_SMEM_HALVES + arow * AS + acol, ph);
        }

        if ((c & 7) == 7) {      // tile epilogue -> g_h fp16
            const int tile = bx + (c >> 3) * GGRID;
            const int r0 = tile * TILE_M + moff + grp;
            const int r1 = r0 + 8;
            #pragma unroll
            for (int j = 0; j < 8; j++) {
                const int col = j * 8 + tig * 2;
                if (r0 < N_NODES)
                    *(uint32_t*)&g_h[(size_t)r0 * D_OUT + col] = pack_h2(acc[j][0], acc[j][1]);
                if (r1 < N_NODES)
                    *(uint32_t*)&g_h[(size_t)r1 * D_OUT + col] = pack_h2(acc[j][2], acc[j][3]);
                acc[j][0] = acc[j][1] = acc[j][2] = acc[j][3] = 0.f;
            }
        }
    }
}

// ---------------- CSR build ---------------------------------------------------
__global__ void k_zero_deg() {
    int i = blockIdx.x * blockDim.x + threadIdx.x;
    if (i < N_NODES) g_deg[i] = 0;
}

__global__ void k_count(const int* __restrict__ rows) {
    int e = blockIdx.x * blockDim.x + threadIdx.x;
    if (e < N_EDGES) atomicAdd(&g_deg[rows[e]], 1);
}

__global__ void k_scan1() {
    __shared__ int wsum[32];
    const int i = blockIdx.x * SCAN_BLK + threadIdx.x;
    const int v = (i < N_NODES) ? g_deg[i] : 0;
    const int lane = threadIdx.x & 31;
    const int w = threadIdx.x >> 5;

    int x = v;
    #pragma unroll
    for (int o = 1; o < 32; o <<= 1) {
        int y = __shfl_up_sync(0xffffffffu, x, o);
        if (lane >= o) x += y;
    }
    if (lane == 31) wsum[w] = x;
    __syncthreads();
    if (w == 0) {
        int s = wsum[lane];
        int t = s;
        #pragma unroll
        for (int o = 1; o < 32; o <<= 1) {
            int y = __shfl_up_sync(0xffffffffu, t, o);
            if (lane >= o) t += y;
        }
        wsum[lane] = t - s;
        if (lane == 31) g_bsum[blockIdx.x] = t;
    }
    __syncthreads();
    const int excl = x - v + wsum[w];
    if (i < N_NODES) g_rowstart[i] = excl;
}

// scan3 with fused block-offset scan (each block redundantly scans g_bsum)
__global__ void k_scan3() {
    __shared__ int s_boff[128];
    __shared__ int wsum[4];
    const int tid = threadIdx.x;
    if (tid < 128) {
        const int lane = tid & 31;
        const int w = tid >> 5;
        const int v = (tid < N_SCAN_BLKS) ? g_bsum[tid] : 0;
        int x = v;
        #pragma unroll
        for (int o = 1; o < 32; o <<= 1) {
            int y = __shfl_up_sync(0xffffffffu, x, o);
            if (lane >= o) x += y;
        }
        if (lane == 31) wsum[w] = x;
        __syncwarp();
        if (tid < 4) { /* serialize tiny */ }
        __syncthreads();
        int woff = 0;
        for (int j = 0; j < w; j++) woff += wsum[j];
        s_boff[tid] = x - v + woff;
    } else {
        __syncthreads();
    }
    __syncthreads();

    const int i = blockIdx.x * SCAN_BLK + tid;
    if (i < N_NODES) {
        const int val = g_rowstart[i] + s_boff[blockIdx.x];
        g_rowstart[i] = val;
        g_cursor[i] = val;
    }
    if (i == 0) g_rowstart[N_NODES] = N_EDGES;
}

__global__ void k_fill(const float* __restrict__ vals,
                       const int* __restrict__ rows,
                       const int* __restrict__ cols) {
    int e = blockIdx.x * blockDim.x + threadIdx.x;
    if (e < N_EDGES) {
        const int r = rows[e];
        const int p = atomicAdd(&g_cursor[r], 1);
        g_csr_col[p] = cols[e];
        g_csr_val[p] = vals[e];
    }
}

// ---------------- SpMM + ReLU: warp per row, 8-wide MLP -----------------------
__global__ void k_spmm(float* __restrict__ out) {
    const int gwarp = (blockIdx.x * blockDim.x + threadIdx.x) >> 5;
    const int lane = threadIdx.x & 31;
    if (gwarp >= N_NODES) return;

    const int s = g_rowstart[gwarp];
    const int e = g_rowstart[gwarp + 1];

    const __half2* __restrict__ h2 = (const __half2*)g_h;
    float2 acc = make_float2(0.f, 0.f);

    for (int j = s; j < e; j += 32) {
        const int jj = j + lane;
        int   c = 0;
        float v = 0.f;
        if (jj < e) {
            c = g_csr_col[jj];
            v = g_csr_val[jj];
        }
        const int cnt = min(32, e - j);
        int i = 0;
        for (; i + 8 <= cnt; i += 8) {
            int   ci[8];
            float vi[8];
            float2 hv[8];
            #pragma unroll
            for (int u = 0; u < 8; u++) {
                ci[u] = __shfl_sync(0xffffffffu, c, i + u);
                vi[u] = __shfl_sync(0xffffffffu, v, i + u);
            }
            #pragma unroll
            for (int u = 0; u < 8; u++)
                hv[u] = __half22float2(h2[(size_t)ci[u] * 32 + lane]);
            #pragma unroll
            for (int u = 0; u < 8; u++) {
                acc.x = fmaf(vi[u], hv[u].x, acc.x);
                acc.y = fmaf(vi[u], hv[u].y, acc.y);
            }
        }
        for (; i < cnt; i++) {
            const int   ci = __shfl_sync(0xffffffffu, c, i);
            const float vi = __shfl_sync(0xffffffffu, v, i);
            const float2 hv = __half22float2(h2[(size_t)ci * 32 + lane]);
            acc.x = fmaf(vi, hv.x, acc.x);
            acc.y = fmaf(vi, hv.y, acc.y);
        }
    }

    acc.x = fmaxf(acc.x, 0.f);
    acc.y = fmaxf(acc.y, 0.f);
    ((float2*)out)[(size_t)gwarp * 32 + lane] = acc;
}

// ---------------- launch ------------------------------------------------------
extern "C" void kernel_launch(void* const* d_in, const int* in_sizes, int n_in,
                              void* d_out, int out_size) {
    const float* X    = (const float*)d_in[0];
    const float* W    = (const float*)d_in[1];
    const float* vals = (const float*)d_in[2];
    const int*   rows = (const int*)d_in[3];
    const int*   cols = (const int*)d_in[4];
    float* out = (float*)d_out;

    static bool attr_set = false;
    if (!attr_set) {
        cudaFuncSetAttribute(k_gemm_tc, cudaFuncAttributeMaxDynamicSharedMemorySize,
                             SMEM_TOTAL);
        attr_set = true;
    }

    // gemm at launch index 4 so the ncu capture slot lands on it
    k_zero_deg<<<(N_NODES + 255) / 256, 256>>>();
    k_count<<<(N_EDGES + 255) / 256, 256>>>(rows);
    k_scan1<<<N_SCAN_BLKS, SCAN_BLK>>>();
    k_gemm_tc<<<GGRID, NTHREADS, SMEM_TOTAL>>>(X, W);
    k_scan3<<<N_SCAN_BLKS, SCAN_BLK>>>();
    k_fill<<<(N_EDGES + 255) / 256, 256>>>(vals, rows, cols);

    k_spmm<<<(N_NODES + 7) / 8, 256>>>(out);
}

// round 7
// speedup vs baseline: 1.1980x; 1.1980x over previous
#include <cuda_runtime.h>
#include <cuda_fp16.h>
#include <cstdint>

#define N_NODES 100000
#define N_EDGES 1600000
#define D_IN    512
#define D_OUT   64

#define SCAN_BLK 1024
#define N_SCAN_BLKS ((N_NODES + SCAN_BLK - 1) / SCAN_BLK)   // 98

#define TILE_M  256
#define TILES   391            // ceil(100000/256)
#define GGRID   152
#define NTHREADS 512

#define BS 72                  // halves per W row in smem (64 + 8 pad)
#define AS 40                  // halves per A row in smem (32 + 8 pad)
#define B_SMEM_HALVES (D_IN * BS)            // 36864  (73728 B)
#define A_SMEM_HALVES (TILE_M * AS)          // 10240 per buffer (20480 B)
#define SMEM_TOTAL ((B_SMEM_HALVES + 2 * A_SMEM_HALVES) * 2)  // 114688 B

// ---------------- scratch -----------------------------------------------------
__device__ __half g_h[N_NODES * D_OUT];      // 12.8 MB fp16
__device__ int   g_deg[N_NODES];
__device__ int   g_rowstart[N_NODES + 1];
__device__ int   g_cursor[N_NODES];
__device__ int   g_bsum[128];
__device__ int   g_csr_col[N_EDGES];
__device__ float g_csr_val[N_EDGES];

// ---------------- helpers -----------------------------------------------------
__device__ __forceinline__ uint32_t smem_u32(const void* p) {
    uint32_t a;
    asm("{ .reg .u64 t; cvta.to.shared.u64 t, %1; cvt.u32.u64 %0, t; }"
        : "=r"(a) : "l"(p));
    return a;
}

__device__ __forceinline__ uint32_t pack_h2(float lo, float hi) {
    __half2 h = __floats2half2_rn(lo, hi);
    return *reinterpret_cast<uint32_t*>(&h);
}

__device__ __forceinline__ void ldsm_x4(uint32_t addr, uint32_t r[4]) {
    asm volatile("ldmatrix.sync.aligned.m8n8.x4.shared.b16 {%0,%1,%2,%3}, [%4];"
                 : "=r"(r[0]), "=r"(r[1]), "=r"(r[2]), "=r"(r[3]) : "r"(addr));
}

__device__ __forceinline__ void ldsm_x4_t(uint32_t addr, uint32_t r[4]) {
    asm volatile("ldmatrix.sync.aligned.m8n8.x4.trans.shared.b16 {%0,%1,%2,%3}, [%4];"
                 : "=r"(r[0]), "=r"(r[1]), "=r"(r[2]), "=r"(r[3]) : "r"(addr));
}

__device__ __forceinline__ void mma_f16(float c[4], const uint32_t a[4],
                                        uint32_t b0, uint32_t b1) {
    asm volatile(
        "mma.sync.aligned.m16n8k16.row.col.f32.f16.f16.f32 "
        "{%0,%1,%2,%3}, {%4,%5,%6,%7}, {%8,%9}, {%0,%1,%2,%3};"
        : "+f"(c[0]), "+f"(c[1]), "+f"(c[2]), "+f"(c[3])
        : "r"(a[0]), "r"(a[1]), "r"(a[2]), "r"(a[3]), "r"(b0), "r"(b1));
}

// ---------------- GEMM: h = X @ W, fp16 mma, depth-2 prefetch -----------------
__global__ __launch_bounds__(NTHREADS, 1) void k_gemm_tc(const float* __restrict__ X,
                                                         const float* __restrict__ W) {
    extern __shared__ __align__(16) __half hsm[];
    __half* const Bsm = hsm;                       // [512][72]
    __half* const Asm = hsm + B_SMEM_HALVES;       // 2 x [256][40]

    const int tid  = threadIdx.x;
    const int bx   = blockIdx.x;
    const int warp = tid >> 5;        // 0..15
    const int lane = tid & 31;
    const int grp  = lane >> 2;
    const int tig  = lane & 3;
    const int moff = warp * 16;

    const uint32_t b_base = smem_u32(Bsm);
    const uint32_t a_base = smem_u32(Asm);

    // ---- W -> smem fp16 [k][n] stride 72 ----
    for (int i = tid * 4; i < D_IN * D_OUT; i += NTHREADS * 4) {
        const int kk = i >> 6, nn = i & 63;
        float4 v = *(const float4*)&W[i];
        *(uint2*)(Bsm + kk * BS + nn) = make_uint2(pack_h2(v.x, v.y), pack_h2(v.z, v.w));
    }

    const int my_tiles = (TILES - bx + GGRID - 1) / GGRID;
    const int nchunks  = my_tiles * 16;            // 16 chunks of 32 cols per tile
    if (nchunks == 0) return;

    const int arow = tid >> 1;            // 0..255
    const int acol = (tid & 1) * 16;      // half-row (16 floats)

    // per-thread global pointer for chunk c: X + grow*D_IN + (c&15)*32 + acol
    #define CHUNK_PTR(c) (X + (size_t)((bx + ((c) >> 4) * GGRID) * TILE_M + arow) * D_IN \
                            + ((c) & 15) * 32 + acol)
    #define CHUNK_OK(c)  ((bx + ((c) >> 4) * GGRID) * TILE_M + arow < N_NODES)

    float4 pf[2][4];

    // prologue: chunk 0 -> buf 0 directly; chunks 1,2 -> pf[1], pf[0]
    {
        const bool ok = CHUNK_OK(0);
        const float* p = CHUNK_PTR(0);
        float4 t[4];
        #pragma unroll
        for (int j = 0; j < 4; j++)
            t[j] = ok ? *(const float4*)(p + 4 * j) : make_float4(0.f, 0.f, 0.f, 0.f);
        __half* d = Asm + arow * AS + acol;
        *(uint4*)d       = make_uint4(pack_h2(t[0].x, t[0].y), pack_h2(t[0].z, t[0].w),
                                      pack_h2(t[1].x, t[1].y), pack_h2(t[1].z, t[1].w));
        *(uint4*)(d + 8) = make_uint4(pack_h2(t[2].x, t[2].y), pack_h2(t[2].z, t[2].w),
                                      pack_h2(t[3].x, t[3].y), pack_h2(t[3].z, t[3].w));
    }
    if (1 < nchunks) {
        const bool ok = CHUNK_OK(1);
        const float* p = CHUNK_PTR(1);
        #pragma unroll
        for (int j = 0; j < 4; j++)
            pf[1][j] = ok ? *(const float4*)(p + 4 * j) : make_float4(0.f, 0.f, 0.f, 0.f);
    }
    if (2 < nchunks) {
        const bool ok = CHUNK_OK(2);
        const float* p = CHUNK_PTR(2);
        #pragma unroll
        for (int j = 0; j < 4; j++)
            pf[0][j] = ok ? *(const float4*)(p + 4 * j) : make_float4(0.f, 0.f, 0.f, 0.f);
    }

    float acc[8][4];
    #pragma unroll
    for (int j = 0; j < 8; j++)
        #pragma unroll
        for (int e = 0; e < 4; e++) acc[j][e] = 0.f;

    const int l15 = lane & 15;
    const int lhi = (lane >> 4) << 3;

    #pragma unroll 2
    for (int c = 0; c < nchunks; c++) {
        __syncthreads();

        // ---- compute chunk c from buf c&1 ----
        const uint32_t abuf = a_base + (uint32_t)(c & 1) * (A_SMEM_HALVES * 2);
        const int kbase = (c & 15) * 32;
        #pragma unroll
        for (int ks = 0; ks < 2; ks++) {
            uint32_t a[4];
            ldsm_x4(abuf + 2 * ((moff + l15) * AS + ks * 16 + lhi), a);

            uint32_t b[8][2];
            const int kb = kbase + ks * 16;
            #pragma unroll
            for (int jj = 0; jj < 4; jj++) {
                uint32_t br[4];
                ldsm_x4_t(b_base + 2 * ((kb + l15) * BS + jj * 16 + lhi), br);
                b[2*jj][0]   = br[0];  b[2*jj][1]   = br[1];
                b[2*jj+1][0] = br[2];  b[2*jj+1][1] = br[3];
            }
            #pragma unroll
            for (int j = 0; j < 8; j++)
                mma_f16(acc[j], a, b[j][0], b[j][1]);
        }

        // ---- convert + store chunk c+1 (loaded 2 iters ago), then reload slot with c+3 ----
        const int p = (c + 1) & 1;
        if (c + 1 < nchunks) {
            __half* d = Asm + (size_t)p * A_SMEM_HALVES + arow * AS + acol;
            *(uint4*)d       = make_uint4(pack_h2(pf[p][0].x, pf[p][0].y), pack_h2(pf[p][0].z, pf[p][0].w),
                                          pack_h2(pf[p][1].x, pf[p][1].y), pack_h2(pf[p][1].z, pf[p][1].w));
            *(uint4*)(d + 8) = make_uint4(pack_h2(pf[p][2].x, pf[p][2].y), pack_h2(pf[p][2].z, pf[p][2].w),
                                          pack_h2(pf[p][3].x, pf[p][3].y), pack_h2(pf[p][3].z, pf[p][3].w));
        }
        if (c + 3 < nchunks) {
            const bool ok = CHUNK_OK(c + 3);
            const float* gp = CHUNK_PTR(c + 3);
            #pragma unroll
            for (int j = 0; j < 4; j++)
                pf[p][j] = ok ? *(const float4*)(gp + 4 * j) : make_float4(0.f, 0.f, 0.f, 0.f);
        }

        if ((c & 15) == 15) {    // tile epilogue -> g_h fp16
            const int tile = bx + (c >> 4) * GGRID;
            const int r0 = tile * TILE_M + moff + grp;
            const int r1 = r0 + 8;
            #pragma unroll
            for (int j = 0; j < 8; j++) {
                const int col = j * 8 + tig * 2;
                if (r0 < N_NODES)
                    *(uint32_t*)&g_h[(size_t)r0 * D_OUT + col] = pack_h2(acc[j][0], acc[j][1]);
                if (r1 < N_NODES)
                    *(uint32_t*)&g_h[(size_t)r1 * D_OUT + col] = pack_h2(acc[j][2], acc[j][3]);
                acc[j][0] = acc[j][1] = acc[j][2] = acc[j][3] = 0.f;
            }
        }
    }
    #undef CHUNK_PTR
    #undef CHUNK_OK
}

// ---------------- CSR build ---------------------------------------------------
__global__ void k_zero_deg() {
    int i = blockIdx.x * blockDim.x + threadIdx.x;
    if (i < N_NODES) g_deg[i] = 0;
}

__global__ void k_count(const int* __restrict__ rows) {
    int e = blockIdx.x * blockDim.x + threadIdx.x;
    if (e < N_EDGES) atomicAdd(&g_deg[rows[e]], 1);
}

__global__ void k_scan1() {
    __shared__ int wsum[32];
    const int i = blockIdx.x * SCAN_BLK + threadIdx.x;
    const int v = (i < N_NODES) ? g_deg[i] : 0;
    const int lane = threadIdx.x & 31;
    const int w = threadIdx.x >> 5;

    int x = v;
    #pragma unroll
    for (int o = 1; o < 32; o <<= 1) {
        int y = __shfl_up_sync(0xffffffffu, x, o);
        if (lane >= o) x += y;
    }
    if (lane == 31) wsum[w] = x;
    __syncthreads();
    if (w == 0) {
        int s = wsum[lane];
        int t = s;
        #pragma unroll
        for (int o = 1; o < 32; o <<= 1) {
            int y = __shfl_up_sync(0xffffffffu, t, o);
            if (lane >= o) t += y;
        }
        wsum[lane] = t - s;
        if (lane == 31) g_bsum[blockIdx.x] = t;
    }
    __syncthreads();
    const int excl = x - v + wsum[w];
    if (i < N_NODES) g_rowstart[i] = excl;
}

// scan3 with fused block-offset scan (each block redundantly scans g_bsum)
__global__ void k_scan3() {
    __shared__ int s_boff[128];
    __shared__ int wsum[4];
    const int tid = threadIdx.x;
    if (tid < 128) {
        const int lane = tid & 31;
        const int w = tid >> 5;
        const int v = (tid < N_SCAN_BLKS) ? g_bsum[tid] : 0;
        int x = v;
        #pragma unroll
        for (int o = 1; o < 32; o <<= 1) {
            int y = __shfl_up_sync(0xffffffffu, x, o);
            if (lane >= o) x += y;
        }
        if (lane == 31) wsum[w] = x;
    }
    __syncthreads();
    if (tid < 128) {
        const int lane = tid & 31;
        const int w = tid >> 5;
        const int v = (tid < N_SCAN_BLKS) ? g_bsum[tid] : 0;
        int x = v;
        #pragma unroll
        for (int o = 1; o < 32; o <<= 1) {
            int y = __shfl_up_sync(0xffffffffu, x, o);
            if (lane >= o) x += y;
        }
        int woff = 0;
        for (int j = 0; j < w; j++) woff += wsum[j];
        s_boff[tid] = x - v + woff;
    }
    __syncthreads();

    const int i = blockIdx.x * SCAN_BLK + tid;
    if (i < N_NODES) {
        const int val = g_rowstart[i] + s_boff[blockIdx.x];
        g_rowstart[i] = val;
        g_cursor[i] = val;
    }
    if (i == 0) g_rowstart[N_NODES] = N_EDGES;
}

__global__ void k_fill(const float* __restrict__ vals,
                       const int* __restrict__ rows,
                       const int* __restrict__ cols) {
    int e = blockIdx.x * blockDim.x + threadIdx.x;
    if (e < N_EDGES) {
        const int r = rows[e];
        const int p = atomicAdd(&g_cursor[r], 1);
        g_csr_col[p] = cols[e];
        g_csr_val[p] = vals[e];
    }
}

// ---------------- SpMM + ReLU: warp per row, 8-wide MLP -----------------------
__global__ void k_spmm(float* __restrict__ out) {
    const int gwarp = (blockIdx.x * blockDim.x + threadIdx.x) >> 5;
    const int lane = threadIdx.x & 31;
    if (gwarp >= N_NODES) return;

    const int s = g_rowstart[gwarp];
    const int e = g_rowstart[gwarp + 1];

    const __half2* __restrict__ h2 = (const __half2*)g_h;
    float2 acc = make_float2(0.f, 0.f);

    for (int j = s; j < e; j += 32) {
        const int jj = j + lane;
        int   c = 0;
        float v = 0.f;
        if (jj < e) {
            c = g_csr_col[jj];
            v = g_csr_val[jj];
        }
        const int cnt = min(32, e - j);
        int i = 0;
        for (; i + 8 <= cnt; i += 8) {
            int   ci[8];
            float vi[8];
            float2 hv[8];
            #pragma unroll
            for (int u = 0; u < 8; u++) {
                ci[u] = __shfl_sync(0xffffffffu, c, i + u);
                vi[u] = __shfl_sync(0xffffffffu, v, i + u);
            }
            #pragma unroll
            for (int u = 0; u < 8; u++)
                hv[u] = __half22float2(h2[(size_t)ci[u] * 32 + lane]);
            #pragma unroll
            for (int u = 0; u < 8; u++) {
                acc.x = fmaf(vi[u], hv[u].x, acc.x);
                acc.y = fmaf(vi[u], hv[u].y, acc.y);
            }
        }
        for (; i < cnt; i++) {
            const int   ci = __shfl_sync(0xffffffffu, c, i);
            const float vi = __shfl_sync(0xffffffffu, v, i);
            const float2 hv = __half22float2(h2[(size_t)ci * 32 + lane]);
            acc.x = fmaf(vi, hv.x, acc.x);
            acc.y = fmaf(vi, hv.y, acc.y);
        }
    }

    acc.x = fmaxf(acc.x, 0.f);
    acc.y = fmaxf(acc.y, 0.f);
    ((float2*)out)[(size_t)gwarp * 32 + lane] = acc;
}

// ---------------- launch ------------------------------------------------------
extern "C" void kernel_launch(void* const* d_in, const int* in_sizes, int n_in,
                              void* d_out, int out_size) {
    const float* X    = (const float*)d_in[0];
    const float* W    = (const float*)d_in[1];
    const float* vals = (const float*)d_in[2];
    const int*   rows = (const int*)d_in[3];
    const int*   cols = (const int*)d_in[4];
    float* out = (float*)d_out;

    static bool attr_set = false;
    if (!attr_set) {
        cudaFuncSetAttribute(k_gemm_tc, cudaFuncAttributeMaxDynamicSharedMemorySize,
                             SMEM_TOTAL);
        attr_set = true;
    }

    // gemm at launch index 3 so the ncu capture slot lands on it
    k_zero_deg<<<(N_NODES + 255) / 256, 256>>>();
    k_count<<<(N_EDGES + 255) / 256, 256>>>(rows);
    k_scan1<<<N_SCAN_BLKS, SCAN_BLK>>>();
    k_gemm_tc<<<GGRID, NTHREADS, SMEM_TOTAL>>>(X, W);
    k_scan3<<<N_SCAN_BLKS, SCAN_BLK>>>();
    k_fill<<<(N_EDGES + 255) / 256, 256>>>(vals, rows, cols);

    k_spmm<<<(N_NODES + 7) / 8, 256>>>(out);
}

// round 8
// speedup vs baseline: 1.2042x; 1.0052x over previous
#include <cuda_runtime.h>
#include <cuda_fp16.h>
#include <cstdint>

#define N_NODES 100000
#define N_EDGES 1600000
#define D_IN    512
#define D_OUT   64

#define SCAN_BLK 1024
#define N_SCAN_BLKS ((N_NODES + SCAN_BLK - 1) / SCAN_BLK)   // 98

#define TILE_M  128
#define TILES   782            // ceil(100000/128)
#define GGRID   304            // 2 persistent CTAs per SM
#define NTHREADS 256

#define AS 40                  // halves per A row in smem (32 + 8 pad)
#define A_SMEM_HALVES (TILE_M * AS)          // 5120 (10240 B) per buffer
#define B_SMEM_HALVES (D_IN * D_OUT)         // 32768 (65536 B), swizzled 128B rows
#define SMEM_TOTAL ((B_SMEM_HALVES + 2 * A_SMEM_HALVES) * 2)  // 86016 B

// ---------------- scratch -----------------------------------------------------
__device__ __half g_h[N_NODES * D_OUT];      // 12.8 MB fp16
__device__ int   g_deg[N_NODES];
__device__ int   g_rowstart[N_NODES + 1];
__device__ int   g_cursor[N_NODES];
__device__ int   g_bsum[128];
__device__ int   g_csr_col[N_EDGES];
__device__ float g_csr_val[N_EDGES];

// ---------------- helpers -----------------------------------------------------
__device__ __forceinline__ uint32_t smem_u32(const void* p) {
    uint32_t a;
    asm("{ .reg .u64 t; cvta.to.shared.u64 t, %1; cvt.u32.u64 %0, t; }"
        : "=r"(a) : "l"(p));
    return a;
}

__device__ __forceinline__ uint32_t pack_h2(float lo, float hi) {
    __half2 h = __floats2half2_rn(lo, hi);
    return *reinterpret_cast<uint32_t*>(&h);
}

__device__ __forceinline__ void ldsm_x4(uint32_t addr, uint32_t r[4]) {
    asm volatile("ldmatrix.sync.aligned.m8n8.x4.shared.b16 {%0,%1,%2,%3}, [%4];"
                 : "=r"(r[0]), "=r"(r[1]), "=r"(r[2]), "=r"(r[3]) : "r"(addr));
}

__device__ __forceinline__ void ldsm_x4_t(uint32_t addr, uint32_t r[4]) {
    asm volatile("ldmatrix.sync.aligned.m8n8.x4.trans.shared.b16 {%0,%1,%2,%3}, [%4];"
                 : "=r"(r[0]), "=r"(r[1]), "=r"(r[2]), "=r"(r[3]) : "r"(addr));
}

__device__ __forceinline__ void mma_f16(float c[4], const uint32_t a[4],
                                        uint32_t b0, uint32_t b1) {
    asm volatile(
        "mma.sync.aligned.m16n8k16.row.col.f32.f16.f16.f32 "
        "{%0,%1,%2,%3}, {%4,%5,%6,%7}, {%8,%9}, {%0,%1,%2,%3};"
        : "+f"(c[0]), "+f"(c[1]), "+f"(c[2]), "+f"(c[3])
        : "r"(a[0]), "r"(a[1]), "r"(a[2]), "r"(a[3]), "r"(b0), "r"(b1));
}

// ---------------- GEMM: h = X @ W, fp16 mma, 2 CTAs/SM ------------------------
__global__ __launch_bounds__(NTHREADS, 2) void k_gemm_tc(const float* __restrict__ X,
                                                         const float* __restrict__ W) {
    extern __shared__ __align__(16) __half hsm[];
    __half* const Bsm = hsm;                       // [512] rows x 128B, XOR-swizzled
    __half* const Asm = hsm + B_SMEM_HALVES;       // 2 x [128][40]

    const int tid  = threadIdx.x;
    const int bx   = blockIdx.x;
    const int warp = tid >> 5;        // 0..7
    const int lane = tid & 31;
    const int grp  = lane >> 2;
    const int tig  = lane & 3;
    const int moff = warp * 16;       // 0..112

    const uint32_t b_base = smem_u32(Bsm);
    const uint32_t a_base = smem_u32(Asm);

    // ---- W -> smem fp16, 128B rows, 16B-unit XOR swizzle: u ^= (k & 7) ----
    for (int i = tid * 8; i < D_IN * D_OUT; i += NTHREADS * 8) {
        const int kk = i >> 6, nn = i & 63;
        float4 v0 = *(const float4*)&W[i];
        float4 v1 = *(const float4*)&W[i + 4];
        const int u = (nn >> 3) ^ (kk & 7);
        *(uint4*)(Bsm + kk * 64 + u * 8) =
            make_uint4(pack_h2(v0.x, v0.y), pack_h2(v0.z, v0.w),
                       pack_h2(v1.x, v1.y), pack_h2(v1.z, v1.w));
    }

    const int my_tiles = (TILES - bx + GGRID - 1) / GGRID;
    const int nchunks  = my_tiles * 16;            // 16 chunks of 32 cols per tile
    if (nchunks == 0) return;

    const int arow = tid >> 1;            // 0..127
    const int acol = (tid & 1) * 16;      // half-row (16 floats)

    float4 pf[4];
    {   // prologue: chunk 0 -> buffer 0
        const int grow = bx * TILE_M + arow;
        const float* p = X + (size_t)grow * D_IN + acol;
        const bool ok = grow < N_NODES;
        #pragma unroll
        for (int j = 0; j < 4; j++)
            pf[j] = ok ? *(const float4*)(p + 4 * j) : make_float4(0.f, 0.f, 0.f, 0.f);
        __half* d = Asm + arow * AS + acol;
        *(uint4*)d       = make_uint4(pack_h2(pf[0].x, pf[0].y), pack_h2(pf[0].z, pf[0].w),
                                      pack_h2(pf[1].x, pf[1].y), pack_h2(pf[1].z, pf[1].w));
        *(uint4*)(d + 8) = make_uint4(pack_h2(pf[2].x, pf[2].y), pack_h2(pf[2].z, pf[2].w),
                                      pack_h2(pf[3].x, pf[3].y), pack_h2(pf[3].z, pf[3].w));
    }

    float acc[8][4];
    #pragma unroll
    for (int j = 0; j < 8; j++)
        #pragma unroll
        for (int e = 0; e < 4; e++) acc[j][e] = 0.f;

    const int l15 = lane & 15;
    const int lhi16 = lane >> 4;          // which 16B half within a 32B pair

    for (int c = 0; c < nchunks; c++) {
        if (c + 1 < nchunks) {   // prefetch next chunk into regs
            const int tile = bx + ((c + 1) >> 4) * GGRID;
            const int grow = tile * TILE_M + arow;
            const int k0   = ((c + 1) & 15) * 32 + acol;
            const float* p = X + (size_t)grow * D_IN + k0;
            const bool ok = grow < N_NODES;
            #pragma unroll
            for (int j = 0; j < 4; j++)
                pf[j] = ok ? *(const float4*)(p + 4 * j) : make_float4(0.f, 0.f, 0.f, 0.f);
        }

        __syncthreads();

        // ---- compute chunk c ----
        const uint32_t abuf = a_base + (uint32_t)(c & 1) * (A_SMEM_HALVES * 2);
        const int kbase = (c & 15) * 32;
        #pragma unroll
        for (int ks = 0; ks < 2; ks++) {
            uint32_t a[4];
            ldsm_x4(abuf + 2 * ((moff + l15) * AS + ks * 16) + (lhi16 << 4), a);

            uint32_t b[8][2];
            const int kb = kbase + ks * 16;
            const int brow = kb + l15;
            const uint32_t brbase = b_base + brow * 128;
            const int bsw = brow & 7;
            #pragma unroll
            for (int jj = 0; jj < 4; jj++) {
                uint32_t br[4];
                const int u = ((jj << 1) | lhi16) ^ bsw;
                ldsm_x4_t(brbase + (u << 4), br);
                b[2*jj][0]   = br[0];  b[2*jj][1]   = br[1];
                b[2*jj+1][0] = br[2];  b[2*jj+1][1] = br[3];
            }
            #pragma unroll
            for (int j = 0; j < 8; j++)
                mma_f16(acc[j], a, b[j][0], b[j][1]);
        }

        if (c + 1 < nchunks) {   // convert + store next chunk to other buffer
            __half* d = Asm + (size_t)((c + 1) & 1) * A_SMEM_HALVES + arow * AS + acol;
            *(uint4*)d       = make_uint4(pack_h2(pf[0].x, pf[0].y), pack_h2(pf[0].z, pf[0].w),
                                          pack_h2(pf[1].x, pf[1].y), pack_h2(pf[1].z, pf[1].w));
            *(uint4*)(d + 8) = make_uint4(pack_h2(pf[2].x, pf[2].y), pack_h2(pf[2].z, pf[2].w),
                                          pack_h2(pf[3].x, pf[3].y), pack_h2(pf[3].z, pf[3].w));
        }

        if ((c & 15) == 15) {    // tile epilogue -> g_h fp16
            const int tile = bx + (c >> 4) * GGRID;
            const int r0 = tile * TILE_M + moff + grp;
            const int r1 = r0 + 8;
            #pragma unroll
            for (int j = 0; j < 8; j++) {
                const int col = j * 8 + tig * 2;
                if (r0 < N_NODES)
                    *(uint32_t*)&g_h[(size_t)r0 * D_OUT + col] = pack_h2(acc[j][0], acc[j][1]);
                if (r1 < N_NODES)
                    *(uint32_t*)&g_h[(size_t)r1 * D_OUT + col] = pack_h2(acc[j][2], acc[j][3]);
                acc[j][0] = acc[j][1] = acc[j][2] = acc[j][3] = 0.f;
            }
        }
    }
}

// ---------------- CSR build ---------------------------------------------------
__global__ void k_zero_deg() {
    int i = blockIdx.x * blockDim.x + threadIdx.x;
    if (i < N_NODES) g_deg[i] = 0;
}

__global__ void k_count(const int* __restrict__ rows) {
    int e = blockIdx.x * blockDim.x + threadIdx.x;
    if (e < N_EDGES) atomicAdd(&g_deg[rows[e]], 1);
}

__global__ void k_scan1() {
    __shared__ int wsum[32];
    const int i = blockIdx.x * SCAN_BLK + threadIdx.x;
    const int v = (i < N_NODES) ? g_deg[i] : 0;
    const int lane = threadIdx.x & 31;
    const int w = threadIdx.x >> 5;

    int x = v;
    #pragma unroll
    for (int o = 1; o < 32; o <<= 1) {
        int y = __shfl_up_sync(0xffffffffu, x, o);
        if (lane >= o) x += y;
    }
    if (lane == 31) wsum[w] = x;
    __syncthreads();
    if (w == 0) {
        int s = wsum[lane];
        int t = s;
        #pragma unroll
        for (int o = 1; o < 32; o <<= 1) {
            int y = __shfl_up_sync(0xffffffffu, t, o);
            if (lane >= o) t += y;
        }
        wsum[lane] = t - s;
        if (lane == 31) g_bsum[blockIdx.x] = t;
    }
    __syncthreads();
    const int excl = x - v + wsum[w];
    if (i < N_NODES) g_rowstart[i] = excl;
}

// scan3 with fused block-offset scan (each block redundantly scans g_bsum)
__global__ void k_scan3() {
    __shared__ int s_boff[128];
    __shared__ int wsum[4];
    const int tid = threadIdx.x;
    if (tid < 128) {
        const int lane = tid & 31;
        const int w = tid >> 5;
        const int v = (tid < N_SCAN_BLKS) ? g_bsum[tid] : 0;
        int x = v;
        #pragma unroll
        for (int o = 1; o < 32; o <<= 1) {
            int y = __shfl_up_sync(0xffffffffu, x, o);
            if (lane >= o) x += y;
        }
        if (lane == 31) wsum[w] = x;
    }
    __syncthreads();
    if (tid < 128) {
        const int lane = tid & 31;
        const int w = tid >> 5;
        const int v = (tid < N_SCAN_BLKS) ? g_bsum[tid] : 0;
        int x = v;
        #pragma unroll
        for (int o = 1; o < 32; o <<= 1) {
            int y = __shfl_up_sync(0xffffffffu, x, o);
            if (lane >= o) x += y;
        }
        int woff = 0;
        for (int j = 0; j < w; j++) woff += wsum[j];
        s_boff[tid] = x - v + woff;
    }
    __syncthreads();

    const int i = blockIdx.x * SCAN_BLK + tid;
    if (i < N_NODES) {
        const int val = g_rowstart[i] + s_boff[blockIdx.x];
        g_rowstart[i] = val;
        g_cursor[i] = val;
    }
    if (i == 0) g_rowstart[N_NODES] = N_EDGES;
}

__global__ void k_fill(const float* __restrict__ vals,
                       const int* __restrict__ rows,
                       const int* __restrict__ cols) {
    int e = blockIdx.x * blockDim.x + threadIdx.x;
    if (e < N_EDGES) {
        const int r = rows[e];
        const int p = atomicAdd(&g_cursor[r], 1);
        g_csr_col[p] = cols[e];
        g_csr_val[p] = vals[e];
    }
}

// ---------------- SpMM + ReLU: warp per row, 8-wide MLP -----------------------
__global__ void k_spmm(float* __restrict__ out) {
    const int gwarp = (blockIdx.x * blockDim.x + threadIdx.x) >> 5;
    const int lane = threadIdx.x & 31;
    if (gwarp >= N_NODES) return;

    const int s = g_rowstart[gwarp];
    const int e = g_rowstart[gwarp + 1];

    const __half2* __restrict__ h2 = (const __half2*)g_h;
    float2 acc = make_float2(0.f, 0.f);

    for (int j = s; j < e; j += 32) {
        const int jj = j + lane;
        int   c = 0;
        float v = 0.f;
        if (jj < e) {
            c = g_csr_col[jj];
            v = g_csr_val[jj];
        }
        const int cnt = min(32, e - j);
        int i = 0;
        for (; i + 8 <= cnt; i += 8) {
            int   ci[8];
            float vi[8];
            float2 hv[8];
            #pragma unroll
            for (int u = 0; u < 8; u++) {
                ci[u] = __shfl_sync(0xffffffffu, c, i + u);
                vi[u] = __shfl_sync(0xffffffffu, v, i + u);
            }
            #pragma unroll
            for (int u = 0; u < 8; u++)
                hv[u] = __half22float2(h2[(size_t)ci[u] * 32 + lane]);
            #pragma unroll
            for (int u = 0; u < 8; u++) {
                acc.x = fmaf(vi[u], hv[u].x, acc.x);
                acc.y = fmaf(vi[u], hv[u].y, acc.y);
            }
        }
        for (; i < cnt; i++) {
            const int   ci = __shfl_sync(0xffffffffu, c, i);
            const float vi = __shfl_sync(0xffffffffu, v, i);
            const float2 hv = __half22float2(h2[(size_t)ci * 32 + lane]);
            acc.x = fmaf(vi, hv.x, acc.x);
            acc.y = fmaf(vi, hv.y, acc.y);
        }
    }

    acc.x = fmaxf(acc.x, 0.f);
    acc.y = fmaxf(acc.y, 0.f);
    ((float2*)out)[(size_t)gwarp * 32 + lane] = acc;
}

// ---------------- launch ------------------------------------------------------
extern "C" void kernel_launch(void* const* d_in, const int* in_sizes, int n_in,
                              void* d_out, int out_size) {
    const float* X    = (const float*)d_in[0];
    const float* W    = (const float*)d_in[1];
    const float* vals = (const float*)d_in[2];
    const int*   rows = (const int*)d_in[3];
    const int*   cols = (const int*)d_in[4];
    float* out = (float*)d_out;

    static bool attr_set = false;
    if (!attr_set) {
        cudaFuncSetAttribute(k_gemm_tc, cudaFuncAttributeMaxDynamicSharedMemorySize,
                             SMEM_TOTAL);
        attr_set = true;
    }

    // gemm at launch index 3 so the ncu capture slot lands on it
    k_zero_deg<<<(N_NODES + 255) / 256, 256>>>();
    k_count<<<(N_EDGES + 255) / 256, 256>>>(rows);
    k_scan1<<<N_SCAN_BLKS, SCAN_BLK>>>();
    k_gemm_tc<<<GGRID, NTHREADS, SMEM_TOTAL>>>(X, W);
    k_scan3<<<N_SCAN_BLKS, SCAN_BLK>>>();
    k_fill<<<(N_EDGES + 255) / 256, 256>>>(vals, rows, cols);

    k_spmm<<<(N_NODES + 7) / 8, 256>>>(out);
}

// round 9
// speedup vs baseline: 1.2342x; 1.0249x over previous
#include <cuda_runtime.h>
#include <cuda_fp16.h>
#include <cstdint>

#define N_NODES 100000
#define N_EDGES 1600000
#define D_IN    512
#define D_OUT   64

#define SCAN_BLK 1024
#define N_SCAN_BLKS ((N_NODES + SCAN_BLK - 1) / SCAN_BLK)   // 98

#define TILE_M  128
#define TILES   782            // ceil(100000/128)
#define GGRID   456            // 3 persistent CTAs per SM
#define NTHREADS 256

#define B_SMEM_HALVES (D_IN * D_OUT)         // 32768 halves = 65536 B, swizzled 128B rows
#define SMEM_TOTAL (B_SMEM_HALVES * 2)       // 65536 B

// ---------------- scratch -----------------------------------------------------
__device__ __half g_h[N_NODES * D_OUT];      // 12.8 MB fp16
__device__ int   g_deg[N_NODES];
__device__ int   g_rowstart[N_NODES + 1];
__device__ int   g_cursor[N_NODES];
__device__ int   g_bsum[128];
__device__ int   g_csr_col[N_EDGES];
__device__ float g_csr_val[N_EDGES];

// ---------------- helpers -----------------------------------------------------
__device__ __forceinline__ uint32_t smem_u32(const void* p) {
    uint32_t a;
    asm("{ .reg .u64 t; cvta.to.shared.u64 t, %1; cvt.u32.u64 %0, t; }"
        : "=r"(a) : "l"(p));
    return a;
}

__device__ __forceinline__ uint32_t pack_h2(float lo, float hi) {
    __half2 h = __floats2half2_rn(lo, hi);
    return *reinterpret_cast<uint32_t*>(&h);
}

__device__ __forceinline__ void ldsm_x4_t(uint32_t addr, uint32_t r[4]) {
    asm volatile("ldmatrix.sync.aligned.m8n8.x4.trans.shared.b16 {%0,%1,%2,%3}, [%4];"
                 : "=r"(r[0]), "=r"(r[1]), "=r"(r[2]), "=r"(r[3]) : "r"(addr));
}

__device__ __forceinline__ void mma_f16(float c[4], const uint32_t a[4],
                                        uint32_t b0, uint32_t b1) {
    asm volatile(
        "mma.sync.aligned.m16n8k16.row.col.f32.f16.f16.f32 "
        "{%0,%1,%2,%3}, {%4,%5,%6,%7}, {%8,%9}, {%0,%1,%2,%3};"
        : "+f"(c[0]), "+f"(c[1]), "+f"(c[2]), "+f"(c[3])
        : "r"(a[0]), "r"(a[1]), "r"(a[2]), "r"(a[3]), "r"(b0), "r"(b1));
}

// ---------------- GEMM: barrier-free, A direct from gmem ----------------------
__global__ __launch_bounds__(NTHREADS, 3) void k_gemm_tc(const float* __restrict__ X,
                                                         const float* __restrict__ W) {
    extern __shared__ __align__(16) __half Bsm[];  // [512] rows x 128B, XOR-swizzled

    const int tid  = threadIdx.x;
    const int warp = tid >> 5;        // 0..7
    const int lane = tid & 31;
    const int grp  = lane >> 2;       // 0..7
    const int tig  = lane & 3;        // 0..3
    const int moff = warp * 16;

    const uint32_t b_base = smem_u32(Bsm);

    // ---- W -> smem fp16, 128B rows, 16B-unit XOR swizzle: u ^= (k & 7) ----
    for (int i = tid * 8; i < D_IN * D_OUT; i += NTHREADS * 8) {
        const int kk = i >> 6, nn = i & 63;
        float4 v0 = *(const float4*)&W[i];
        float4 v1 = *(const float4*)&W[i + 4];
        const int u = (nn >> 3) ^ (kk & 7);
        *(uint4*)(Bsm + kk * 64 + u * 8) =
            make_uint4(pack_h2(v0.x, v0.y), pack_h2(v0.z, v0.w),
                       pack_h2(v1.x, v1.y), pack_h2(v1.z, v1.w));
    }
    __syncthreads();     // only barrier: B ready, read-only afterwards

    const int l15 = lane & 15;
    const int lhi16 = lane >> 4;

    for (int tile = blockIdx.x; tile < TILES; tile += GGRID) {
        const int r0 = tile * TILE_M + moff + grp;
        const int r1 = r0 + 8;
        const bool ok0 = r0 < N_NODES;
        const bool ok1 = r1 < N_NODES;
        // per-lane A pointers (col offset 2*tig baked in)
        const float* pA0 = X + (size_t)(ok0 ? r0 : 0) * D_IN + 2 * tig;
        const float* pA1 = X + (size_t)(ok1 ? r1 : 0) * D_IN + 2 * tig;

        float acc[8][4];
        #pragma unroll
        for (int j = 0; j < 8; j++)
            #pragma unroll
            for (int e = 0; e < 4; e++) acc[j][e] = 0.f;

        // software pipeline over 32 k-steps of 16
        float2 v0, v1, v2, v3;
        v0 = ok0 ? *(const float2*)(pA0)     : make_float2(0.f, 0.f);
        v1 = ok1 ? *(const float2*)(pA1)     : make_float2(0.f, 0.f);
        v2 = ok0 ? *(const float2*)(pA0 + 8) : make_float2(0.f, 0.f);
        v3 = ok1 ? *(const float2*)(pA1 + 8) : make_float2(0.f, 0.f);

        #pragma unroll 4
        for (int kk = 0; kk < 32; kk++) {
            uint32_t a[4];
            a[0] = pack_h2(v0.x, v0.y);
            a[1] = pack_h2(v1.x, v1.y);
            a[2] = pack_h2(v2.x, v2.y);
            a[3] = pack_h2(v3.x, v3.y);

            if (kk + 1 < 32) {   // prefetch next k-step
                const int k0 = (kk + 1) * 16;
                v0 = ok0 ? *(const float2*)(pA0 + k0)     : make_float2(0.f, 0.f);
                v1 = ok1 ? *(const float2*)(pA1 + k0)     : make_float2(0.f, 0.f);
                v2 = ok0 ? *(const float2*)(pA0 + k0 + 8) : make_float2(0.f, 0.f);
                v3 = ok1 ? *(const float2*)(pA1 + k0 + 8) : make_float2(0.f, 0.f);
            }

            // B fragments for k-step kk (rows kk*16 + 0..15)
            const int brow = kk * 16 + l15;
            const uint32_t brbase = b_base + brow * 128;
            const int bsw = brow & 7;
            uint32_t b[8][2];
            #pragma unroll
            for (int jj = 0; jj < 4; jj++) {
                uint32_t br[4];
                const int u = ((jj << 1) | lhi16) ^ bsw;
                ldsm_x4_t(brbase + (u << 4), br);
                b[2*jj][0]   = br[0];  b[2*jj][1]   = br[1];
                b[2*jj+1][0] = br[2];  b[2*jj+1][1] = br[3];
            }
            #pragma unroll
            for (int j = 0; j < 8; j++)
                mma_f16(acc[j], a, b[j][0], b[j][1]);
        }

        // epilogue -> g_h fp16
        #pragma unroll
        for (int j = 0; j < 8; j++) {
            const int col = j * 8 + tig * 2;
            if (ok0)
                *(uint32_t*)&g_h[(size_t)r0 * D_OUT + col] = pack_h2(acc[j][0], acc[j][1]);
            if (ok1)
                *(uint32_t*)&g_h[(size_t)r1 * D_OUT + col] = pack_h2(acc[j][2], acc[j][3]);
        }
    }
}

// ---------------- CSR build ---------------------------------------------------
__global__ void k_zero_deg() {
    int i = blockIdx.x * blockDim.x + threadIdx.x;
    if (i < N_NODES) g_deg[i] = 0;
}

__global__ void k_count(const int* __restrict__ rows) {
    int e = blockIdx.x * blockDim.x + threadIdx.x;
    if (e < N_EDGES) atomicAdd(&g_deg[rows[e]], 1);
}

__global__ void k_scan1() {
    __shared__ int wsum[32];
    const int i = blockIdx.x * SCAN_BLK + threadIdx.x;
    const int v = (i < N_NODES) ? g_deg[i] : 0;
    const int lane = threadIdx.x & 31;
    const int w = threadIdx.x >> 5;

    int x = v;
    #pragma unroll
    for (int o = 1; o < 32; o <<= 1) {
        int y = __shfl_up_sync(0xffffffffu, x, o);
        if (lane >= o) x += y;
    }
    if (lane == 31) wsum[w] = x;
    __syncthreads();
    if (w == 0) {
        int s = wsum[lane];
        int t = s;
        #pragma unroll
        for (int o = 1; o < 32; o <<= 1) {
            int y = __shfl_up_sync(0xffffffffu, t, o);
            if (lane >= o) t += y;
        }
        wsum[lane] = t - s;
        if (lane == 31) g_bsum[blockIdx.x] = t;
    }
    __syncthreads();
    const int excl = x - v + wsum[w];
    if (i < N_NODES) g_rowstart[i] = excl;
}

// scan3 with fused block-offset scan
__global__ void k_scan3() {
    __shared__ int s_boff[128];
    __shared__ int wsum[4];
    const int tid = threadIdx.x;
    if (tid < 128) {
        const int lane = tid & 31;
        const int w = tid >> 5;
        const int v = (tid < N_SCAN_BLKS) ? g_bsum[tid] : 0;
        int x = v;
        #pragma unroll
        for (int o = 1; o < 32; o <<= 1) {
            int y = __shfl_up_sync(0xffffffffu, x, o);
            if (lane >= o) x += y;
        }
        if (lane == 31) wsum[w] = x;
    }
    __syncthreads();
    if (tid < 128) {
        const int lane = tid & 31;
        const int w = tid >> 5;
        const int v = (tid < N_SCAN_BLKS) ? g_bsum[tid] : 0;
        int x = v;
        #pragma unroll
        for (int o = 1; o < 32; o <<= 1) {
            int y = __shfl_up_sync(0xffffffffu, x, o);
            if (lane >= o) x += y;
        }
        int woff = 0;
        for (int j = 0; j < w; j++) woff += wsum[j];
        s_boff[tid] = x - v + woff;
    }
    __syncthreads();

    const int i = blockIdx.x * SCAN_BLK + tid;
    if (i < N_NODES) {
        const int val = g_rowstart[i] + s_boff[blockIdx.x];
        g_rowstart[i] = val;
        g_cursor[i] = val;
    }
    if (i == 0) g_rowstart[N_NODES] = N_EDGES;
}

__global__ void k_fill(const float* __restrict__ vals,
                       const int* __restrict__ rows,
                       const int* __restrict__ cols) {
    int e = blockIdx.x * blockDim.x + threadIdx.x;
    if (e < N_EDGES) {
        const int r = rows[e];
        const int p = atomicAdd(&g_cursor[r], 1);
        g_csr_col[p] = cols[e];
        g_csr_val[p] = vals[e];
    }
}

// ---------------- SpMM + ReLU: warp per row, 8-wide MLP -----------------------
__global__ void k_spmm(float* __restrict__ out) {
    const int gwarp = (blockIdx.x * blockDim.x + threadIdx.x) >> 5;
    const int lane = threadIdx.x & 31;
    if (gwarp >= N_NODES) return;

    const int s = g_rowstart[gwarp];
    const int e = g_rowstart[gwarp + 1];

    const __half2* __restrict__ h2 = (const __half2*)g_h;
    float2 acc = make_float2(0.f, 0.f);

    for (int j = s; j < e; j += 32) {
        const int jj = j + lane;
        int   c = 0;
        float v = 0.f;
        if (jj < e) {
            c = g_csr_col[jj];
            v = g_csr_val[jj];
        }
        const int cnt = min(32, e - j);
        int i = 0;
        for (; i + 8 <= cnt; i += 8) {
            int   ci[8];
            float vi[8];
            float2 hv[8];
            #pragma unroll
            for (int u = 0; u < 8; u++) {
                ci[u] = __shfl_sync(0xffffffffu, c, i + u);
                vi[u] = __shfl_sync(0xffffffffu, v, i + u);
            }
            #pragma unroll
            for (int u = 0; u < 8; u++)
                hv[u] = __half22float2(h2[(size_t)ci[u] * 32 + lane]);
            #pragma unroll
            for (int u = 0; u < 8; u++) {
                acc.x = fmaf(vi[u], hv[u].x, acc.x);
                acc.y = fmaf(vi[u], hv[u].y, acc.y);
            }
        }
        for (; i < cnt; i++) {
            const int   ci = __shfl_sync(0xffffffffu, c, i);
            const float vi = __shfl_sync(0xffffffffu, v, i);
            const float2 hv = __half22float2(h2[(size_t)ci * 32 + lane]);
            acc.x = fmaf(vi, hv.x, acc.x);
            acc.y = fmaf(vi, hv.y, acc.y);
        }
    }

    acc.x = fmaxf(acc.x, 0.f);
    acc.y = fmaxf(acc.y, 0.f);
    ((float2*)out)[(size_t)gwarp * 32 + lane] = acc;
}

// ---------------- launch ------------------------------------------------------
extern "C" void kernel_launch(void* const* d_in, const int* in_sizes, int n_in,
                              void* d_out, int out_size) {
    const float* X    = (const float*)d_in[0];
    const float* W    = (const float*)d_in[1];
    const float* vals = (const float*)d_in[2];
    const int*   rows = (const int*)d_in[3];
    const int*   cols = (const int*)d_in[4];
    float* out = (float*)d_out;

    static bool attr_set = false;
    if (!attr_set) {
        cudaFuncSetAttribute(k_gemm_tc, cudaFuncAttributeMaxDynamicSharedMemorySize,
                             SMEM_TOTAL);
        attr_set = true;
    }

    // gemm at launch index 3 so the ncu capture slot lands on it
    k_zero_deg<<<(N_NODES + 255) / 256, 256>>>();
    k_count<<<(N_EDGES + 255) / 256, 256>>>(rows);
    k_scan1<<<N_SCAN_BLKS, SCAN_BLK>>>();
    k_gemm_tc<<<GGRID, NTHREADS, SMEM_TOTAL>>>(X, W);
    k_scan3<<<N_SCAN_BLKS, SCAN_BLK>>>();
    k_fill<<<(N_EDGES + 255) / 256, 256>>>(vals, rows, cols);

    k_spmm<<<(N_NODES + 7) / 8, 256>>>(out);
}

// round 10
// speedup vs baseline: 1.3220x; 1.0711x over previous
#include <cuda_runtime.h>
#include <cuda_fp16.h>
#include <cstdint>

#define N_NODES 100000
#define N_EDGES 1600000
#define D_IN    512
#define D_OUT   64

#define SCAN_BLK 1024
#define N_SCAN_BLKS ((N_NODES + SCAN_BLK - 1) / SCAN_BLK)   // 98

#define GGRID   456            // 3 persistent CTAs per SM
#define NTHREADS 256
#define N_UNITS (N_NODES / 16)          // 6250 warp work units (exact)
#define TOTAL_WARPS (GGRID * 8)         // 3648

#define B_SMEM_HALVES (D_IN * D_OUT)    // 32768 halves = 65536 B
#define SMEM_TOTAL (B_SMEM_HALVES * 2)  // 65536 B

// ---------------- scratch -----------------------------------------------------
__device__ __half g_h[N_NODES * D_OUT];      // 12.8 MB fp16
__device__ int   g_deg[N_NODES];
__device__ int   g_rowstart[N_NODES + 1];
__device__ int   g_cursor[N_NODES];
__device__ int   g_bsum[128];
__device__ int   g_csr_col[N_EDGES];
__device__ float g_csr_val[N_EDGES];
__device__ int   g_unit_ctr;

// ---------------- helpers -----------------------------------------------------
__device__ __forceinline__ uint32_t smem_u32(const void* p) {
    uint32_t a;
    asm("{ .reg .u64 t; cvta.to.shared.u64 t, %1; cvt.u32.u64 %0, t; }"
        : "=r"(a) : "l"(p));
    return a;
}

__device__ __forceinline__ uint32_t pack_h2(float lo, float hi) {
    __half2 h = __floats2half2_rn(lo, hi);
    return *reinterpret_cast<uint32_t*>(&h);
}

__device__ __forceinline__ void ldsm_x4_t(uint32_t addr, uint32_t r[4]) {
    asm volatile("ldmatrix.sync.aligned.m8n8.x4.trans.shared.b16 {%0,%1,%2,%3}, [%4];"
                 : "=r"(r[0]), "=r"(r[1]), "=r"(r[2]), "=r"(r[3]) : "r"(addr));
}

__device__ __forceinline__ void mma_f16(float c[4], const uint32_t a[4],
                                        uint32_t b0, uint32_t b1) {
    asm volatile(
        "mma.sync.aligned.m16n8k16.row.col.f32.f16.f16.f32 "
        "{%0,%1,%2,%3}, {%4,%5,%6,%7}, {%8,%9}, {%0,%1,%2,%3};"
        : "+f"(c[0]), "+f"(c[1]), "+f"(c[2]), "+f"(c[3])
        : "r"(a[0]), "r"(a[1]), "r"(a[2]), "r"(a[3]), "r"(b0), "r"(b1));
}

// ---------------- GEMM: barrier-free, per-warp queue, float4 A ----------------
// k-permutation within each 16-group (A slots <-> W rows), so one float4 load
// per row supplies all 4 A-fragment halves of a k-step.
__global__ __launch_bounds__(NTHREADS, 3) void k_gemm_tc(const float* __restrict__ X,
                                                         const float* __restrict__ W) {
    extern __shared__ __align__(16) __half Bsm[];  // [512] rows x 128B, XOR-swizzled

    const int tid  = threadIdx.x;
    const int warp = tid >> 5;        // 0..7
    const int lane = tid & 31;
    const int grp  = lane >> 2;       // 0..7
    const int tig  = lane & 3;        // 0..3

    const uint32_t b_base = smem_u32(Bsm);

    // ---- W -> smem fp16, rows k-permuted (perm-inverse), XOR-16B swizzled ----
    for (int i = tid * 8; i < D_IN * D_OUT; i += NTHREADS * 8) {
        const int kk = i >> 6, nn = i & 63;
        const int kl = kk & 15, kh = kk & ~15;
        const int q = kl >> 2, r = kl & 3;
        const int s = (r < 2) ? (2 * q + r) : (8 + 2 * q + (r - 2));
        const int row = kh | s;
        float4 v0 = *(const float4*)&W[i];
        float4 v1 = *(const float4*)&W[i + 4];
        const int u = (nn >> 3) ^ (row & 7);
        *(uint4*)(Bsm + row * 64 + u * 8) =
            make_uint4(pack_h2(v0.x, v0.y), pack_h2(v0.z, v0.w),
                       pack_h2(v1.x, v1.y), pack_h2(v1.z, v1.w));
    }
    __syncthreads();     // only barrier: B ready, read-only afterwards

    const int l15 = lane & 15;
    const int lhi16 = lane >> 4;

    int unit = blockIdx.x * 8 + warp;

    while (unit < N_UNITS) {
        const int r0 = unit * 16 + grp;          // always < N_NODES (exact division)
        const int r1 = r0 + 8;
        const float* pA0 = X + (size_t)r0 * D_IN + 4 * tig;
        const float* pA1 = X + (size_t)r1 * D_IN + 4 * tig;

        float acc[8][4];
        #pragma unroll
        for (int j = 0; j < 8; j++)
            #pragma unroll
            for (int e = 0; e < 4; e++) acc[j][e] = 0.f;

        float4 v0 = *(const float4*)(pA0);
        float4 v1 = *(const float4*)(pA1);

        #pragma unroll 4
        for (int kk = 0; kk < 32; kk++) {
            uint32_t a[4];
            a[0] = pack_h2(v0.x, v0.y);
            a[1] = pack_h2(v1.x, v1.y);
            a[2] = pack_h2(v0.z, v0.w);
            a[3] = pack_h2(v1.z, v1.w);

            if (kk + 1 < 32) {   // prefetch next k-step (16 floats ahead)
                v0 = *(const float4*)(pA0 + (kk + 1) * 16);
                v1 = *(const float4*)(pA1 + (kk + 1) * 16);
            }

            const int brow = kk * 16 + l15;
            const uint32_t brbase = b_base + brow * 128;
            const int bsw = brow & 7;
            uint32_t b[8][2];
            #pragma unroll
            for (int jj = 0; jj < 4; jj++) {
                uint32_t br[4];
                const int u = ((jj << 1) | lhi16) ^ bsw;
                ldsm_x4_t(brbase + (u << 4), br);
                b[2*jj][0]   = br[0];  b[2*jj][1]   = br[1];
                b[2*jj+1][0] = br[2];  b[2*jj+1][1] = br[3];
            }
            #pragma unroll
            for (int j = 0; j < 8; j++)
                mma_f16(acc[j], a, b[j][0], b[j][1]);
        }

        // next unit (overlap atomic latency with epilogue)
        int nxt = 0;
        if (lane == 0) nxt = atomicAdd(&g_unit_ctr, 1);

        // epilogue -> g_h fp16
        #pragma unroll
        for (int j = 0; j < 8; j++) {
            const int col = j * 8 + tig * 2;
            *(uint32_t*)&g_h[(size_t)r0 * D_OUT + col] = pack_h2(acc[j][0], acc[j][1]);
            *(uint32_t*)&g_h[(size_t)r1 * D_OUT + col] = pack_h2(acc[j][2], acc[j][3]);
        }

        unit = __shfl_sync(0xffffffffu, nxt, 0);
    }
}

// ---------------- CSR build ---------------------------------------------------
__global__ void k_zero_deg() {
    int i = blockIdx.x * blockDim.x + threadIdx.x;
    if (i < N_NODES) g_deg[i] = 0;
    if (i == 0) g_unit_ctr = TOTAL_WARPS;
}

__global__ void k_count(const int* __restrict__ rows) {
    int e = blockIdx.x * blockDim.x + threadIdx.x;
    if (e < N_EDGES) atomicAdd(&g_deg[rows[e]], 1);
}

__global__ void k_scan1() {
    __shared__ int wsum[32];
    const int i = blockIdx.x * SCAN_BLK + threadIdx.x;
    const int v = (i < N_NODES) ? g_deg[i] : 0;
    const int lane = threadIdx.x & 31;
    const int w = threadIdx.x >> 5;

    int x = v;
    #pragma unroll
    for (int o = 1; o < 32; o <<= 1) {
        int y = __shfl_up_sync(0xffffffffu, x, o);
        if (lane >= o) x += y;
    }
    if (lane == 31) wsum[w] = x;
    __syncthreads();
    if (w == 0) {
        int s = wsum[lane];
        int t = s;
        #pragma unroll
        for (int o = 1; o < 32; o <<= 1) {
            int y = __shfl_up_sync(0xffffffffu, t, o);
            if (lane >= o) t += y;
        }
        wsum[lane] = t - s;
        if (lane == 31) g_bsum[blockIdx.x] = t;
    }
    __syncthreads();
    const int excl = x - v + wsum[w];
    if (i < N_NODES) g_rowstart[i] = excl;
}

// scan3 with fused block-offset scan
__global__ void k_scan3() {
    __shared__ int s_boff[128];
    __shared__ int wsum[4];
    const int tid = threadIdx.x;
    if (tid < 128) {
        const int lane = tid & 31;
        const int w = tid >> 5;
        const int v = (tid < N_SCAN_BLKS) ? g_bsum[tid] : 0;
        int x = v;
        #pragma unroll
        for (int o = 1; o < 32; o <<= 1) {
            int y = __shfl_up_sync(0xffffffffu, x, o);
            if (lane >= o) x += y;
        }
        if (lane == 31) wsum[w] = x;
    }
    __syncthreads();
    if (tid < 128) {
        const int lane = tid & 31;
        const int w = tid >> 5;
        const int v = (tid < N_SCAN_BLKS) ? g_bsum[tid] : 0;
        int x = v;
        #pragma unroll
        for (int o = 1; o < 32; o <<= 1) {
            int y = __shfl_up_sync(0xffffffffu, x, o);
            if (lane >= o) x += y;
        }
        int woff = 0;
        for (int j = 0; j < w; j++) woff += wsum[j];
        s_boff[tid] = x - v + woff;
    }
    __syncthreads();

    const int i = blockIdx.x * SCAN_BLK + tid;
    if (i < N_NODES) {
        const int val = g_rowstart[i] + s_boff[blockIdx.x];
        g_rowstart[i] = val;
        g_cursor[i] = val;
    }
    if (i == 0) g_rowstart[N_NODES] = N_EDGES;
}

__global__ void k_fill(const float* __restrict__ vals,
                       const int* __restrict__ rows,
                       const int* __restrict__ cols) {
    int e = blockIdx.x * blockDim.x + threadIdx.x;
    if (e < N_EDGES) {
        const int r = rows[e];
        const int p = atomicAdd(&g_cursor[r], 1);
        g_csr_col[p] = cols[e];
        g_csr_val[p] = vals[e];
    }
}

// ---------------- SpMM + ReLU: warp per row, 8-wide MLP -----------------------
__global__ void k_spmm(float* __restrict__ out) {
    const int gwarp = (blockIdx.x * blockDim.x + threadIdx.x) >> 5;
    const int lane = threadIdx.x & 31;
    if (gwarp >= N_NODES) return;

    const int s = g_rowstart[gwarp];
    const int e = g_rowstart[gwarp + 1];

    const __half2* __restrict__ h2 = (const __half2*)g_h;
    float2 acc = make_float2(0.f, 0.f);

    for (int j = s; j < e; j += 32) {
        const int jj = j + lane;
        int   c = 0;
        float v = 0.f;
        if (jj < e) {
            c = g_csr_col[jj];
            v = g_csr_val[jj];
        }
        const int cnt = min(32, e - j);
        int i = 0;
        for (; i + 8 <= cnt; i += 8) {
            int   ci[8];
            float vi[8];
            float2 hv[8];
            #pragma unroll
            for (int u = 0; u < 8; u++) {
                ci[u] = __shfl_sync(0xffffffffu, c, i + u);
                vi[u] = __shfl_sync(0xffffffffu, v, i + u);
            }
            #pragma unroll
            for (int u = 0; u < 8; u++)
                hv[u] = __half22float2(h2[(size_t)ci[u] * 32 + lane]);
            #pragma unroll
            for (int u = 0; u < 8; u++) {
                acc.x = fmaf(vi[u], hv[u].x, acc.x);
                acc.y = fmaf(vi[u], hv[u].y, acc.y);
            }
        }
        for (; i < cnt; i++) {
            const int   ci = __shfl_sync(0xffffffffu, c, i);
            const float vi = __shfl_sync(0xffffffffu, v, i);
            const float2 hv = __half22float2(h2[(size_t)ci * 32 + lane]);
            acc.x = fmaf(vi, hv.x, acc.x);
            acc.y = fmaf(vi, hv.y, acc.y);
        }
    }

    acc.x = fmaxf(acc.x, 0.f);
    acc.y = fmaxf(acc.y, 0.f);
    ((float2*)out)[(size_t)gwarp * 32 + lane] = acc;
}

// ---------------- launch ------------------------------------------------------
extern "C" void kernel_launch(void* const* d_in, const int* in_sizes, int n_in,
                              void* d_out, int out_size) {
    const float* X    = (const float*)d_in[0];
    const float* W    = (const float*)d_in[1];
    const float* vals = (const float*)d_in[2];
    const int*   rows = (const int*)d_in[3];
    const int*   cols = (const int*)d_in[4];
    float* out = (float*)d_out;

    static bool attr_set = false;
    if (!attr_set) {
        cudaFuncSetAttribute(k_gemm_tc, cudaFuncAttributeMaxDynamicSharedMemorySize,
                             SMEM_TOTAL);
        attr_set = true;
    }

    // gemm at launch index 3 so the ncu capture slot lands on it
    k_zero_deg<<<(N_NODES + 255) / 256, 256>>>();
    k_count<<<(N_EDGES + 255) / 256, 256>>>(rows);
    k_scan1<<<N_SCAN_BLKS, SCAN_BLK>>>();
    k_gemm_tc<<<GGRID, NTHREADS, SMEM_TOTAL>>>(X, W);
    k_scan3<<<N_SCAN_BLKS, SCAN_BLK>>>();
    k_fill<<<(N_EDGES + 255) / 256, 256>>>(vals, rows, cols);

    k_spmm<<<(N_NODES + 7) / 8, 256>>>(out);
}

// round 11
// speedup vs baseline: 1.4715x; 1.1131x over previous
#include <cuda_runtime.h>
#include <cuda_fp16.h>
#include <cstdint>

#define N_NODES 100000
#define N_EDGES 1600000
#define D_IN    512
#define D_OUT   64

#define SCAN_BLK 1024
#define N_SCAN_BLKS ((N_NODES + SCAN_BLK - 1) / SCAN_BLK)   // 98

#define GGRID   456            // 3 persistent CTAs per SM
#define NTHREADS 256
#define N_UNITS (N_NODES / 16)          // 6250 warp work units (exact)
#define TOTAL_WARPS (GGRID * 8)         // 3648

#define B_SMEM_HALVES (D_IN * D_OUT)    // 32768 halves = 65536 B
#define SMEM_TOTAL (B_SMEM_HALVES * 2)  // 65536 B

// ---------------- scratch -----------------------------------------------------
__device__ __half g_h[N_NODES * D_OUT];      // 12.8 MB fp16
__device__ int   g_deg[N_NODES];
__device__ int   g_rowstart[N_NODES + 1];
__device__ int   g_cursor[N_NODES];
__device__ int   g_bsum[128];
__device__ int2  g_csr[N_EDGES];             // (col, val-as-int)
__device__ int   g_unit_ctr;

// ---------------- helpers -----------------------------------------------------
__device__ __forceinline__ uint32_t smem_u32(const void* p) {
    uint32_t a;
    asm("{ .reg .u64 t; cvta.to.shared.u64 t, %1; cvt.u32.u64 %0, t; }"
        : "=r"(a) : "l"(p));
    return a;
}

__device__ __forceinline__ uint32_t pack_h2(float lo, float hi) {
    __half2 h = __floats2half2_rn(lo, hi);
    return *reinterpret_cast<uint32_t*>(&h);
}

__device__ __forceinline__ void ldsm_x4_t(uint32_t addr, uint32_t r[4]) {
    asm volatile("ldmatrix.sync.aligned.m8n8.x4.trans.shared.b16 {%0,%1,%2,%3}, [%4];"
                 : "=r"(r[0]), "=r"(r[1]), "=r"(r[2]), "=r"(r[3]) : "r"(addr));
}

__device__ __forceinline__ void mma_f16(float c[4], const uint32_t a[4],
                                        uint32_t b0, uint32_t b1) {
    asm volatile(
        "mma.sync.aligned.m16n8k16.row.col.f32.f16.f16.f32 "
        "{%0,%1,%2,%3}, {%4,%5,%6,%7}, {%8,%9}, {%0,%1,%2,%3};"
        : "+f"(c[0]), "+f"(c[1]), "+f"(c[2]), "+f"(c[3])
        : "r"(a[0]), "r"(a[1]), "r"(a[2]), "r"(a[3]), "r"(b0), "r"(b1));
}

// ---------------- GEMM: barrier-free, per-warp queue, depth-2 prefetch --------
__global__ __launch_bounds__(NTHREADS, 3) void k_gemm_tc(const float* __restrict__ X,
                                                         const float* __restrict__ W) {
    extern __shared__ __align__(16) __half Bsm[];  // [512] rows x 128B, XOR-swizzled

    const int tid  = threadIdx.x;
    const int warp = tid >> 5;
    const int lane = tid & 31;
    const int grp  = lane >> 2;
    const int tig  = lane & 3;

    const uint32_t b_base = smem_u32(Bsm);

    // ---- W -> smem fp16, rows k-permuted (perm-inverse), XOR-16B swizzled ----
    for (int i = tid * 8; i < D_IN * D_OUT; i += NTHREADS * 8) {
        const int kk = i >> 6, nn = i & 63;
        const int kl = kk & 15, kh = kk & ~15;
        const int q = kl >> 2, r = kl & 3;
        const int s = (r < 2) ? (2 * q + r) : (8 + 2 * q + (r - 2));
        const int row = kh | s;
        float4 v0 = *(const float4*)&W[i];
        float4 v1 = *(const float4*)&W[i + 4];
        const int u = (nn >> 3) ^ (row & 7);
        *(uint4*)(Bsm + row * 64 + u * 8) =
            make_uint4(pack_h2(v0.x, v0.y), pack_h2(v0.z, v0.w),
                       pack_h2(v1.x, v1.y), pack_h2(v1.z, v1.w));
    }
    __syncthreads();

    const int l15 = lane & 15;
    const int lhi16 = lane >> 4;

    int unit = blockIdx.x * 8 + warp;

    while (unit < N_UNITS) {
        const int r0 = unit * 16 + grp;
        const int r1 = r0 + 8;
        const float* pA0 = X + (size_t)r0 * D_IN + 4 * tig;
        const float* pA1 = X + (size_t)r1 * D_IN + 4 * tig;

        float acc[8][4];
        #pragma unroll
        for (int j = 0; j < 8; j++)
            #pragma unroll
            for (int e = 0; e < 4; e++) acc[j][e] = 0.f;

        float4 v[2][2];
        v[0][0] = *(const float4*)(pA0);
        v[0][1] = *(const float4*)(pA1);
        v[1][0] = *(const float4*)(pA0 + 16);
        v[1][1] = *(const float4*)(pA1 + 16);

        #pragma unroll 4
        for (int kk = 0; kk < 32; kk++) {
            const int sl = kk & 1;
            uint32_t a[4];
            a[0] = pack_h2(v[sl][0].x, v[sl][0].y);
            a[1] = pack_h2(v[sl][1].x, v[sl][1].y);
            a[2] = pack_h2(v[sl][0].z, v[sl][0].w);
            a[3] = pack_h2(v[sl][1].z, v[sl][1].w);

            if (kk + 2 < 32) {   // refill this slot with k-step kk+2
                v[sl][0] = *(const float4*)(pA0 + (kk + 2) * 16);
                v[sl][1] = *(const float4*)(pA1 + (kk + 2) * 16);
            }

            const int brow = kk * 16 + l15;
            const uint32_t brbase = b_base + brow * 128;
            const int bsw = brow & 7;
            uint32_t b[8][2];
            #pragma unroll
            for (int jj = 0; jj < 4; jj++) {
                uint32_t br[4];
                const int u = ((jj << 1) | lhi16) ^ bsw;
                ldsm_x4_t(brbase + (u << 4), br);
                b[2*jj][0]   = br[0];  b[2*jj][1]   = br[1];
                b[2*jj+1][0] = br[2];  b[2*jj+1][1] = br[3];
            }
            #pragma unroll
            for (int j = 0; j < 8; j++)
                mma_f16(acc[j], a, b[j][0], b[j][1]);
        }

        int nxt = 0;
        if (lane == 0) nxt = atomicAdd(&g_unit_ctr, 1);

        #pragma unroll
        for (int j = 0; j < 8; j++) {
            const int col = j * 8 + tig * 2;
            *(uint32_t*)&g_h[(size_t)r0 * D_OUT + col] = pack_h2(acc[j][0], acc[j][1]);
            *(uint32_t*)&g_h[(size_t)r1 * D_OUT + col] = pack_h2(acc[j][2], acc[j][3]);
        }

        unit = __shfl_sync(0xffffffffu, nxt, 0);
    }
}

// ---------------- CSR build ---------------------------------------------------
__global__ void k_zero_deg() {
    int i = blockIdx.x * blockDim.x + threadIdx.x;
    if (i < N_NODES) g_deg[i] = 0;
    if (i == 0) g_unit_ctr = TOTAL_WARPS;
}

__global__ void k_count(const int* __restrict__ rows) {
    int e = blockIdx.x * blockDim.x + threadIdx.x;
    if (e < N_EDGES) atomicAdd(&g_deg[rows[e]], 1);
}

__global__ void k_scan1() {
    __shared__ int wsum[32];
    const int i = blockIdx.x * SCAN_BLK + threadIdx.x;
    const int v = (i < N_NODES) ? g_deg[i] : 0;
    const int lane = threadIdx.x & 31;
    const int w = threadIdx.x >> 5;

    int x = v;
    #pragma unroll
    for (int o = 1; o < 32; o <<= 1) {
        int y = __shfl_up_sync(0xffffffffu, x, o);
        if (lane >= o) x += y;
    }
    if (lane == 31) wsum[w] = x;
    __syncthreads();
    if (w == 0) {
        int s = wsum[lane];
        int t = s;
        #pragma unroll
        for (int o = 1; o < 32; o <<= 1) {
            int y = __shfl_up_sync(0xffffffffu, t, o);
            if (lane >= o) t += y;
        }
        wsum[lane] = t - s;
        if (lane == 31) g_bsum[blockIdx.x] = t;
    }
    __syncthreads();
    const int excl = x - v + wsum[w];
    if (i < N_NODES) g_rowstart[i] = excl;
}

__global__ void k_scan3() {
    __shared__ int s_boff[128];
    __shared__ int wsum[4];
    const int tid = threadIdx.x;
    if (tid < 128) {
        const int lane = tid & 31;
        const int w = tid >> 5;
        const int v = (tid < N_SCAN_BLKS) ? g_bsum[tid] : 0;
        int x = v;
        #pragma unroll
        for (int o = 1; o < 32; o <<= 1) {
            int y = __shfl_up_sync(0xffffffffu, x, o);
            if (lane >= o) x += y;
        }
        if (lane == 31) wsum[w] = x;
    }
    __syncthreads();
    if (tid < 128) {
        const int lane = tid & 31;
        const int w = tid >> 5;
        const int v = (tid < N_SCAN_BLKS) ? g_bsum[tid] : 0;
        int x = v;
        #pragma unroll
        for (int o = 1; o < 32; o <<= 1) {
            int y = __shfl_up_sync(0xffffffffu, x, o);
            if (lane >= o) x += y;
        }
        int woff = 0;
        for (int j = 0; j < w; j++) woff += wsum[j];
        s_boff[tid] = x - v + woff;
    }
    __syncthreads();

    const int i = blockIdx.x * SCAN_BLK + tid;
    if (i < N_NODES) {
        const int val = g_rowstart[i] + s_boff[blockIdx.x];
        g_rowstart[i] = val;
        g_cursor[i] = val;
    }
    if (i == 0) g_rowstart[N_NODES] = N_EDGES;
}

__global__ void k_fill(const float* __restrict__ vals,
                       const int* __restrict__ rows,
                       const int* __restrict__ cols) {
    int e = blockIdx.x * blockDim.x + threadIdx.x;
    if (e < N_EDGES) {
        const int r = rows[e];
        const int p = atomicAdd(&g_cursor[r], 1);
        g_csr[p] = make_int2(cols[e], __float_as_int(vals[e]));
    }
}

// ---------------- SpMM + ReLU: warp per row, 8-wide MLP -----------------------
__global__ void k_spmm(float* __restrict__ out) {
    const int gwarp = (blockIdx.x * blockDim.x + threadIdx.x) >> 5;
    const int lane = threadIdx.x & 31;
    if (gwarp >= N_NODES) return;

    const int s = g_rowstart[gwarp];
    const int e = g_rowstart[gwarp + 1];

    const __half2* __restrict__ h2 = (const __half2*)g_h;
    float2 acc = make_float2(0.f, 0.f);

    for (int j = s; j < e; j += 32) {
        const int jj = j + lane;
        int   c = 0;
        float v = 0.f;
        if (jj < e) {
            int2 cv = g_csr[jj];
            c = cv.x;
            v = __int_as_float(cv.y);
        }
        const int cnt = min(32, e - j);
        int i = 0;
        for (; i + 8 <= cnt; i += 8) {
            int   ci[8];
            float vi[8];
            float2 hv[8];
            #pragma unroll
            for (int u = 0; u < 8; u++) {
                ci[u] = __shfl_sync(0xffffffffu, c, i + u);
                vi[u] = __shfl_sync(0xffffffffu, v, i + u);
            }
            #pragma unroll
            for (int u = 0; u < 8; u++)
                hv[u] = __half22float2(h2[(size_t)ci[u] * 32 + lane]);
            #pragma unroll
            for (int u = 0; u < 8; u++) {
                acc.x = fmaf(vi[u], hv[u].x, acc.x);
                acc.y = fmaf(vi[u], hv[u].y, acc.y);
            }
        }
        for (; i < cnt; i++) {
            const int   ci = __shfl_sync(0xffffffffu, c, i);
            const float vi = __shfl_sync(0xffffffffu, v, i);
            const float2 hv = __half22float2(h2[(size_t)ci * 32 + lane]);
            acc.x = fmaf(vi, hv.x, acc.x);
            acc.y = fmaf(vi, hv.y, acc.y);
        }
    }

    acc.x = fmaxf(acc.x, 0.f);
    acc.y = fmaxf(acc.y, 0.f);
    ((float2*)out)[(size_t)gwarp * 32 + lane] = acc;
}

// ---------------- launch: fork-join so CSR build overlaps GEMM ----------------
extern "C" void kernel_launch(void* const* d_in, const int* in_sizes, int n_in,
                              void* d_out, int out_size) {
    const float* X    = (const float*)d_in[0];
    const float* W    = (const float*)d_in[1];
    const float* vals = (const float*)d_in[2];
    const int*   rows = (const int*)d_in[3];
    const int*   cols = (const int*)d_in[4];
    float* out = (float*)d_out;

    static bool init_done = false;
    static cudaStream_t s2;
    static cudaEvent_t ev_fork, ev_join;
    if (!init_done) {
        cudaFuncSetAttribute(k_gemm_tc, cudaFuncAttributeMaxDynamicSharedMemorySize,
                             SMEM_TOTAL);
        cudaStreamCreateWithFlags(&s2, cudaStreamNonBlocking);
        cudaEventCreateWithFlags(&ev_fork, cudaEventDisableTiming);
        cudaEventCreateWithFlags(&ev_join, cudaEventDisableTiming);
        init_done = true;
    }

    // fork: CSR chain on s2, GEMM on the main (capture) stream
    cudaEventRecord(ev_fork, 0);
    cudaStreamWaitEvent(s2, ev_fork, 0);

    k_zero_deg<<<(N_NODES + 255) / 256, 256, 0, s2>>>();
    k_count<<<(N_EDGES + 255) / 256, 256, 0, s2>>>(rows);
    k_scan1<<<N_SCAN_BLKS, SCAN_BLK, 0, s2>>>();
    k_scan3<<<N_SCAN_BLKS, SCAN_BLK, 0, s2>>>();
    k_fill<<<(N_EDGES + 255) / 256, 256, 0, s2>>>(vals, rows, cols);

    k_gemm_tc<<<GGRID, NTHREADS, SMEM_TOTAL>>>(X, W);

    // join: spmm needs both branches
    cudaEventRecord(ev_join, s2);
    cudaStreamWaitEvent(0, ev_join, 0);

    k_spmm<<<(N_NODES + 7) / 8, 256>>>(out);
}